// round 2
// baseline (speedup 1.0000x reference)
#include <cuda_runtime.h>

#define NB 256   // batch
#define NN 256   // target particles
#define NM 256   // reco particles
#define ND 4     // feature dim

// Scratch for per-batch results: [0..NB): eucl_non_zero, [NB..2*NB): eucl_zero
__device__ float g_part[2 * NB];

__global__ __launch_bounds__(256) void chamfer_kernel(
    const float* __restrict__ target,
    const float* __restrict__ reco,
    const int*   __restrict__ in_pid,
    const int*   __restrict__ out_pid)
{
    __shared__ float4 sxn[NN];    // -2 * target row
    __shared__ float4 syn[NM];    // -2 * reco row
    __shared__ float  sxc[NN];    // ||x||^2 + penx  (penx = 0 or 1e20)
    __shared__ float  syc[NM];    // ||y||^2 + peny
    __shared__ float4 red[256];   // reduction scratch

    const int b = blockIdx.x;
    const int t = threadIdx.x;

    // coalesced loads: 16B per thread
    const float4* tg = (const float4*)(target + (size_t)b * NN * ND);
    const float4* rc = (const float4*)(reco   + (size_t)b * NM * ND);
    float4 xt = tg[t];
    float4 yt = rc[t];

    const int mx = (in_pid[b * NN + t] != 0);
    const int my = (out_pid[b * NM + t] != 0);

    const float n2x = xt.x*xt.x + xt.y*xt.y + xt.z*xt.z + xt.w*xt.w;  // ||x||^2
    const float n2y = yt.x*yt.x + yt.y*yt.y + yt.z*yt.z + yt.w*yt.w;  // ||y||^2

    sxn[t] = make_float4(-2.0f*xt.x, -2.0f*xt.y, -2.0f*xt.z, -2.0f*xt.w);
    syn[t] = make_float4(-2.0f*yt.x, -2.0f*yt.y, -2.0f*yt.z, -2.0f*yt.w);
    sxc[t] = n2x + (mx ? 0.0f : 1e20f);
    syc[t] = n2y + (my ? 0.0f : 1e20f);

    const int nx = __syncthreads_count(mx);
    const int ny = __syncthreads_count(my);

    // ---- pass 1: min over m of (||y_m||^2 + pen_m - 2 x_t . y_m) ----
    // (||x_t||^2 is constant over m -> added after the min)
    float dmin_xy = 3.0e38f;
    #pragma unroll 8
    for (int m = 0; m < NM; ++m) {
        float4 a = syn[m];                    // broadcast LDS.128
        float s = syc[m];                     // broadcast LDS.32
        s = fmaf(a.x, xt.x, s);
        s = fmaf(a.y, xt.y, s);
        s = fmaf(a.z, xt.z, s);
        s = fmaf(a.w, xt.w, s);
        dmin_xy = fminf(dmin_xy, s);
    }
    float d2_xy = fmaxf(dmin_xy + n2x, 0.0f); // clamp cancellation negatives
    float c_sum_xy = mx ? sqrtf(d2_xy) : 0.0f;

    // ---- pass 2: min over n of (||x_n||^2 + pen_n - 2 x_n . y_t) ----
    float dmin_yx = 3.0e38f;
    #pragma unroll 8
    for (int n = 0; n < NN; ++n) {
        float4 a = sxn[n];                    // broadcast LDS.128
        float s = sxc[n];                     // broadcast LDS.32
        s = fmaf(a.x, yt.x, s);
        s = fmaf(a.y, yt.y, s);
        s = fmaf(a.z, yt.z, s);
        s = fmaf(a.w, yt.w, s);
        dmin_yx = fminf(dmin_yx, s);
    }
    float d2_yx = fmaxf(dmin_yx + n2y, 0.0f);
    float c_sum_yx = my ? sqrtf(d2_yx) : 0.0f;

    // per-row norms for edge cases
    float normx = sqrtf(n2x);
    float normy = sqrtf(n2y);
    float c_nrmx  = mx ? normx : 0.0f;        // sum over mask_x of ||x||
    float c_nrmy0 = my ? 0.0f : normy;        // sum over ~mask_y of ||y||

    // ---- block tree reduction of the 4 sums ----
    red[t] = make_float4(c_sum_xy, c_sum_yx, c_nrmx, c_nrmy0);
    __syncthreads();
    #pragma unroll
    for (int s = 128; s > 0; s >>= 1) {
        if (t < s) {
            float4 a = red[t], c = red[t + s];
            a.x += c.x; a.y += c.y; a.z += c.z; a.w += c.w;
            red[t] = a;
        }
        __syncthreads();
    }

    if (t == 0) {
        float4 r = red[0];
        float sum_xy = r.x, sum_yx = r.y, sum_nrmx = r.z, sum_nrmy0 = r.w;
        float n_in  = (float)max(1, nx);
        float n_out = (float)max(1, ny);
        float normal = 0.5f * (sum_xy / n_out + sum_yx / n_in);
        float eucl_non_zero;
        if (ny == 0)       eucl_non_zero = sum_nrmx / n_in;
        else if (nx == 0)  eucl_non_zero = 0.0f;
        else               eucl_non_zero = normal;
        float n_zero = (float)max(1, NM - ny);
        float eucl_zero = sum_nrmy0 / n_zero;
        g_part[b]      = eucl_non_zero;
        g_part[NB + b] = eucl_zero;
    }
}

__global__ __launch_bounds__(256) void finalize_kernel(float* __restrict__ out)
{
    __shared__ float2 red[256];
    int t = threadIdx.x;
    red[t] = make_float2(g_part[t], g_part[NB + t]);
    __syncthreads();
    #pragma unroll
    for (int s = 128; s > 0; s >>= 1) {
        if (t < s) {
            float2 a = red[t], c = red[t + s];
            a.x += c.x; a.y += c.y;
            red[t] = a;
        }
        __syncthreads();
    }
    if (t == 0) {
        out[0] = red[0].x * (1.0f / NB);
        out[1] = red[0].y * (1.0f / NB);
    }
}

extern "C" void kernel_launch(void* const* d_in, const int* in_sizes, int n_in,
                              void* d_out, int out_size)
{
    const float* target = (const float*)d_in[0];
    const float* reco   = (const float*)d_in[1];
    const int*   in_pid = (const int*)d_in[2];
    const int*   out_pid= (const int*)d_in[3];
    float* out = (float*)d_out;

    chamfer_kernel<<<NB, 256>>>(target, reco, in_pid, out_pid);
    finalize_kernel<<<1, 256>>>(out);
}